// round 3
// baseline (speedup 1.0000x reference)
#include <cuda_runtime.h>
#include <cuda_fp16.h>
#include <stdint.h>

// SparseLinear: out[n,64] = segment_sum(value * W[col,:], rows) + bias
// Pipeline: memset bucket counts -> cvt W fp16 -> bucket hist -> bucket scan ->
//           bucket split (Phase A) -> fused in-smem counting sort + warp/row SpMM.

#define OUTF     64
#define NNZ_MAX  4000000
#define INF_MAX  5120
#define RPB      256          // rows per bucket
#define BSHIFT   8
#define MAXBUCK  512
#define CAP      12288        // max items smem-sorted per bucket (mean ~10240, +20 sigma)
#define IPT      16           // items per thread in phase A

__device__ int    g_bcnt[MAXBUCK];
__device__ int    g_bbase[MAXBUCK];
__device__ int    g_bcur[MAXBUCK];
__device__ float2 g_tmp[NNZ_MAX];          // .x = bits((row&255)<<13 | col), .y = value
__device__ __half g_wh[INF_MAX * OUTF];

// ---------------- convert W fp32 -> fp16 ----------------
__global__ void k_cvt(const float* __restrict__ W, int total) {
    int i = blockIdx.x * blockDim.x + threadIdx.x;
    if (i < total) g_wh[i] = __float2half_rn(W[i]);
}

// ---------------- bucket histogram ----------------
__global__ void __launch_bounds__(256)
k_bhist(const int* __restrict__ rows, int nnz) {
    __shared__ int s_h[MAXBUCK];
    int t = threadIdx.x;
    for (int i = t; i < MAXBUCK; i += 256) s_h[i] = 0;
    __syncthreads();
    int base = blockIdx.x * 256 * IPT;
    #pragma unroll
    for (int k = 0; k < IPT; ++k) {
        int i = base + k * 256 + t;
        if (i < nnz) atomicAdd(&s_h[rows[i] >> BSHIFT], 1);
    }
    __syncthreads();
    for (int i = t; i < MAXBUCK; i += 256)
        if (s_h[i]) atomicAdd(&g_bcnt[i], s_h[i]);
}

// ---------------- bucket exclusive scan (1 block, 512 thr) ----------------
__global__ void __launch_bounds__(MAXBUCK) k_bscan() {
    __shared__ int s_w[16];
    int t = threadIdx.x, lane = t & 31, w = t >> 5;
    int v = g_bcnt[t];
    int x = v;
    #pragma unroll
    for (int d = 1; d < 32; d <<= 1) {
        int y = __shfl_up_sync(0xFFFFFFFFu, x, d);
        if (lane >= d) x += y;
    }
    if (lane == 31) s_w[w] = x;
    __syncthreads();
    if (t == 0) {
        int a = 0;
        #pragma unroll
        for (int k = 0; k < 16; ++k) { int tmp = s_w[k]; s_w[k] = a; a += tmp; }
    }
    __syncthreads();
    int base = x - v + s_w[w];
    g_bbase[t] = base;
    g_bcur[t]  = base;
}

// ---------------- Phase A: bucket split ----------------
__global__ void __launch_bounds__(512)
k_split(const int* __restrict__ rows, const int* __restrict__ cols,
        const float* __restrict__ vals, int nnz) {
    __shared__ int s_cnt[MAXBUCK];
    __shared__ int s_base[MAXBUCK];
    int t = threadIdx.x;
    for (int i = t; i < MAXBUCK; i += 512) s_cnt[i] = 0;
    __syncthreads();

    int tile = blockIdx.x * 512 * IPT;
    int rank[IPT], bk[IPT];
    unsigned pk[IPT];
    float vv[IPT];
    #pragma unroll
    for (int k = 0; k < IPT; ++k) {
        int i = tile + k * 512 + t;
        bk[k] = -1;
        if (i < nnz) {
            int r = rows[i];
            bk[k]   = r >> BSHIFT;
            pk[k]   = ((unsigned)(r & (RPB - 1)) << 13) | (unsigned)cols[i];
            vv[k]   = vals[i];
            rank[k] = atomicAdd(&s_cnt[bk[k]], 1);
        }
    }
    __syncthreads();
    for (int i = t; i < MAXBUCK; i += 512)
        s_base[i] = s_cnt[i] ? atomicAdd(&g_bcur[i], s_cnt[i]) : 0;
    __syncthreads();
    #pragma unroll
    for (int k = 0; k < IPT; ++k)
        if (bk[k] >= 0)
            g_tmp[s_base[bk[k]] + rank[k]] = make_float2(__uint_as_float(pk[k]), vv[k]);
}

// ---------------- fused: in-smem counting sort + warp-per-row SpMM ----------------
extern __shared__ char s_raw[];

__global__ void __launch_bounds__(1024)
k_fused(const float* __restrict__ bias, float* __restrict__ out, int n) {
    float2* s_items = (float2*)s_raw;                       // CAP * 8 bytes
    int* s_start = (int*)(s_raw + CAP * sizeof(float2));    // RPB
    int* s_cur   = s_start + RPB;                           // RPB
    __shared__ int s_w[8];

    int b = blockIdx.x;
    int t = threadIdx.x, lane = t & 31, w = t >> 5;
    int base = g_bbase[b];
    int cnt  = g_bcur[b] - base;
    int incap = cnt < CAP ? cnt : CAP;

    if (t < RPB) s_cur[t] = 0;
    __syncthreads();

    // pass 1: histogram rows within bucket
    for (int i = t; i < incap; i += 1024) {
        unsigned u = __float_as_uint(g_tmp[base + i].x);
        atomicAdd(&s_cur[(u >> 13) & (RPB - 1)], 1);
    }
    __syncthreads();

    // block scan of 256 counts
    int v = (t < RPB) ? s_cur[t] : 0;
    int x = v;
    #pragma unroll
    for (int d = 1; d < 32; d <<= 1) {
        int y = __shfl_up_sync(0xFFFFFFFFu, x, d);
        if (lane >= d) x += y;
    }
    if (t < RPB && lane == 31) s_w[w] = x;
    __syncthreads();
    if (t == 0) {
        int a = 0;
        #pragma unroll
        for (int k = 0; k < 8; ++k) { int tmp = s_w[k]; s_w[k] = a; a += tmp; }
    }
    __syncthreads();
    if (t < RPB) {
        int st = x - v + s_w[w];
        s_start[t] = st;
        s_cur[t]   = st;
    }
    __syncthreads();

    // pass 2: place items sorted by row into smem
    for (int i = t; i < incap; i += 1024) {
        float2 it = g_tmp[base + i];
        unsigned u = __float_as_uint(it.x);
        int p = atomicAdd(&s_cur[(u >> 13) & (RPB - 1)], 1);
        s_items[p] = it;
    }
    __syncthreads();

    // SpMM: warp w owns rows {w, w+32, ..., w+224}; lane owns out cols [2l,2l+1]
    const __half2* __restrict__ wh2 = (const __half2*)g_wh;
    float2 bv = ((const float2*)bias)[lane];

    #pragma unroll
    for (int rr = 0; rr < RPB / 32; ++rr) {
        int r8 = w + rr * 32;
        int grow = b * RPB + r8;
        if (grow >= n) break;
        int st = s_start[r8];
        int rc = s_cur[r8] - st;
        float2 acc = bv;
        #pragma unroll 4
        for (int j = 0; j < rc; ++j) {
            float2 p = s_items[st + j];            // broadcast LDS
            unsigned u = __float_as_uint(p.x);
            int col = (int)(u & 0x1FFFu);
            float vv = p.y;
            float2 wf = __half22float2(wh2[col * 32 + lane]);
            acc.x = fmaf(vv, wf.x, acc.x);
            acc.y = fmaf(vv, wf.y, acc.y);
        }
        ((float2*)out)[(size_t)grow * 32 + lane] = acc;
    }

    // overflow tail (cnt > CAP): statistically never; atomicAdd after full block sync
    if (cnt > incap) {
        __syncthreads();
        for (int i = incap + t; i < cnt; i += 1024) {
            float2 it = g_tmp[base + i];
            unsigned u = __float_as_uint(it.x);
            int r8  = (u >> 13) & (RPB - 1);
            int col = (int)(u & 0x1FFFu);
            float vv = it.y;
            int grow = b * RPB + r8;
            if (grow < n) {
                float* o = out + (size_t)grow * OUTF;
                for (int c = 0; c < OUTF; ++c) {
                    float wf = __half2float(g_wh[col * OUTF + c]);
                    atomicAdd(&o[c], vv * wf);
                }
            }
        }
    }
}

// ---------------- launch ----------------
extern "C" void kernel_launch(void* const* d_in, const int* in_sizes, int n_in,
                              void* d_out, int out_size) {
    const int*   index  = (const int*)d_in[0];    // [2, nnz]
    const float* value  = (const float*)d_in[1];  // [nnz]
    const float* weight = (const float*)d_in[3];  // [in_f, 64]
    const float* bias   = (const float*)d_in[4];  // [64]
    float* out = (float*)d_out;

    int nnz  = in_sizes[1];
    int n    = out_size / OUTF;
    int wtot = in_sizes[3];

    const int* rows = index;
    const int* cols = index + nnz;
    int nbuck = (n + RPB - 1) / RPB;

    void* bcnt_ptr = nullptr;
    cudaGetSymbolAddress(&bcnt_ptr, g_bcnt);
    cudaMemsetAsync(bcnt_ptr, 0, MAXBUCK * sizeof(int));

    k_cvt<<<(wtot + 255) / 256, 256>>>(weight, wtot);

    int hb = (nnz + 256 * IPT - 1) / (256 * IPT);
    k_bhist<<<hb, 256>>>(rows, nnz);
    k_bscan<<<1, MAXBUCK>>>();

    int sb = (nnz + 512 * IPT - 1) / (512 * IPT);
    k_split<<<sb, 512>>>(rows, cols, value, nnz);

    size_t smem = CAP * sizeof(float2) + 2 * RPB * sizeof(int);
    cudaFuncSetAttribute(k_fused, cudaFuncAttributeMaxDynamicSharedMemorySize, (int)smem);
    k_fused<<<nbuck, 1024, smem>>>(bias, out, n);
}

// round 4
// speedup vs baseline: 1.0202x; 1.0202x over previous
#include <cuda_runtime.h>
#include <cuda_fp16.h>
#include <stdint.h>

// SparseLinear: out[n,64] = segment_sum(value * W[col,:], rows) + bias
// Pipeline: init heads -> cvt W fp16 -> build per-row linked lists
//           (coalesced item writes, global atomicExch) -> chain-walking SpMM.

#define OUTF    64
#define N_MAX   100096
#define NNZ_MAX 4000000
#define INF_MAX 5120
#define CHAINS  4

__device__ int    g_head[N_MAX];
__device__ int4   g_items[NNZ_MAX];        // {next, col, val_bits, pad}
__device__ __half g_wh[INF_MAX * OUTF];    // fp16 weight copy

// ---------------- init heads to -1 ----------------
__global__ void k_init(int n) {
    int i = blockIdx.x * blockDim.x + threadIdx.x;
    if (i < n) g_head[i] = -1;
}

// ---------------- convert W fp32 -> fp16 ----------------
__global__ void k_cvt(const float* __restrict__ W, int total) {
    int i = blockIdx.x * blockDim.x + threadIdx.x;
    if (i < total) g_wh[i] = __float2half_rn(W[i]);
}

// ---------------- build per-row linked lists ----------------
__global__ void __launch_bounds__(256)
k_build(const int* __restrict__ rows, const int* __restrict__ cols,
        const float* __restrict__ vals, int nnz) {
    int i = blockIdx.x * blockDim.x + threadIdx.x;
    if (i < nnz) {
        int r   = rows[i];
        int old = atomicExch(&g_head[r], i);          // spread global atomic
        g_items[i] = make_int4(old, cols[i], __float_as_int(vals[i]), 0);
    }
}

// ---------------- chain-walking SpMM ----------------
// Warp owns CHAINS consecutive rows, interleaves their chases for MLP.
// Lane l owns output cols [2l, 2l+1] (float2 accumulator per row).
__global__ void __launch_bounds__(512, 3)
k_spmm(const float* __restrict__ bias, float* __restrict__ out, int n) {
    int gw   = (blockIdx.x * blockDim.x + threadIdx.x) >> 5;
    int lane = threadIdx.x & 31;
    int rowbase = gw * CHAINS;
    if (rowbase >= n) return;

    float2 bv = ((const float2*)bias)[lane];
    const __half2* __restrict__ wh2 = (const __half2*)g_wh;

    int    p[CHAINS];
    float2 acc[CHAINS];
    #pragma unroll
    for (int j = 0; j < CHAINS; ++j) {
        int r = rowbase + j;
        p[j]   = (r < n) ? g_head[r] : -1;   // broadcast read, warp-uniform
        acc[j] = bv;
    }

    while (true) {
        bool any = false;
        #pragma unroll
        for (int j = 0; j < CHAINS; ++j) {
            if (p[j] >= 0) {
                int4 it = g_items[p[j]];                 // 16B broadcast, L2-hot
                float2 wf = __half22float2(__ldg(&wh2[it.y * 32 + lane]));
                float  v  = __int_as_float(it.z);
                acc[j].x = fmaf(v, wf.x, acc[j].x);
                acc[j].y = fmaf(v, wf.y, acc[j].y);
                p[j] = it.x;                             // chase (critical path)
                any = true;
            }
        }
        if (!any) break;
    }

    #pragma unroll
    for (int j = 0; j < CHAINS; ++j) {
        int r = rowbase + j;
        if (r < n) ((float2*)out)[(size_t)r * 32 + lane] = acc[j];
    }
}

// ---------------- launch ----------------
extern "C" void kernel_launch(void* const* d_in, const int* in_sizes, int n_in,
                              void* d_out, int out_size) {
    const int*   index  = (const int*)d_in[0];    // [2, nnz]
    const float* value  = (const float*)d_in[1];  // [nnz]
    const float* weight = (const float*)d_in[3];  // [in_f, 64]
    const float* bias   = (const float*)d_in[4];  // [64]
    float* out = (float*)d_out;

    int nnz  = in_sizes[1];
    int n    = out_size / OUTF;
    int wtot = in_sizes[3];

    const int* rows = index;
    const int* cols = index + nnz;

    k_init<<<(n + 255) / 256, 256>>>(n);
    k_cvt<<<(wtot + 255) / 256, 256>>>(weight, wtot);
    k_build<<<(nnz + 255) / 256, 256>>>(rows, cols, value, nnz);

    int warps = (n + CHAINS - 1) / CHAINS;          // one warp per CHAINS rows
    int blocks = (warps * 32 + 511) / 512;
    k_spmm<<<blocks, 512>>>(bias, out, n);
}

// round 5
// speedup vs baseline: 1.1371x; 1.1147x over previous
#include <cuda_runtime.h>
#include <cuda_fp16.h>
#include <stdint.h>

// SparseLinear: out[n,64] = segment_sum(value * W[col,:], rows) + bias
// Pipeline: memset counts -> cvt W fp16 -> hist(+rank) -> lookback scan ->
//           scatter 4B packed (col<<16|fp16val) -> warp/row SpMM.

#define OUTF 64
#define N_MAX 100032
#define NNZ_MAX 4000000
#define CHUNK 1024
#define MAXBLK 256
#define INF_MAX 5120

__device__ int                g_counts[N_MAX];
__device__ int                g_offsets[N_MAX];
__device__ unsigned long long g_status[MAXBLK];   // (flag<<32)|value; 1=agg, 2=prefix
__device__ unsigned short     g_rank[NNZ_MAX];
__device__ unsigned           g_pack[NNZ_MAX];    // col<<16 | fp16(value)
__device__ __half             g_wh[INF_MAX * OUTF];

// ---------------- convert W fp32 -> fp16 ----------------
__global__ void k_cvt(const float* __restrict__ W, int total) {
    int i = blockIdx.x * blockDim.x + threadIdx.x;
    if (i < total) g_wh[i] = __float2half_rn(W[i]);
}

// ---------------- histogram + per-element rank, zero scan status ----------------
__global__ void k_hist(const int* __restrict__ rows, int nnz, int nb) {
    int i = blockIdx.x * blockDim.x + threadIdx.x;
    if (i < nb) g_status[i] = 0ULL;
    if (i < nnz) {
        int r = rows[i];
        g_rank[i] = (unsigned short)atomicAdd(&g_counts[r], 1);
    }
}

// ---------------- single-pass exclusive scan (decoupled lookback) ----------------
__device__ __forceinline__ int warp_incl_scan(int x, int lane) {
    #pragma unroll
    for (int d = 1; d < 32; d <<= 1) {
        int y = __shfl_up_sync(0xFFFFFFFFu, x, d);
        if (lane >= d) x += y;
    }
    return x;
}

__global__ void __launch_bounds__(CHUNK) k_scan(int n) {
    int b = blockIdx.x, t = threadIdx.x;
    int lane = t & 31, w = t >> 5;
    int i = b * CHUNK + t;
    int v = (i < n) ? g_counts[i] : 0;

    int x = warp_incl_scan(v, lane);
    __shared__ int wsum[32];
    if (lane == 31) wsum[w] = x;
    __syncthreads();
    if (w == 0) wsum[lane] = warp_incl_scan(wsum[lane], lane);
    __syncthreads();
    int incl  = x + (w ? wsum[w - 1] : 0);
    int total = wsum[31];

    __shared__ int s_base;
    if (w == 0) {
        int base = 0;
        if (b == 0) {
            if (lane == 0)
                atomicExch(&g_status[0], (2ULL << 32) | (unsigned)total);
        } else {
            if (lane == 0)
                atomicExch(&g_status[b], (1ULL << 32) | (unsigned)total);
            int j = b - 1;
            while (true) {
                int idx = j - lane;
                unsigned flag; int val;
                if (idx >= 0) {
                    unsigned long long st;
                    do { st = atomicAdd(&g_status[idx], 0ULL); }
                    while ((st >> 32) == 0ULL);
                    flag = (unsigned)(st >> 32);
                    val  = (int)(unsigned)st;
                } else { flag = 2u; val = 0; }
                unsigned pmask = __ballot_sync(0xFFFFFFFFu, flag == 2u);
                if (pmask) {
                    int lead = __ffs(pmask) - 1;
                    int c = (lane <= lead) ? val : 0;
                    #pragma unroll
                    for (int d = 16; d; d >>= 1) c += __shfl_down_sync(0xFFFFFFFFu, c, d);
                    base += __shfl_sync(0xFFFFFFFFu, c, 0);
                    break;
                } else {
                    int c = val;
                    #pragma unroll
                    for (int d = 16; d; d >>= 1) c += __shfl_down_sync(0xFFFFFFFFu, c, d);
                    base += __shfl_sync(0xFFFFFFFFu, c, 0);
                    j -= 32;
                }
            }
            if (lane == 0)
                atomicExch(&g_status[b], (2ULL << 32) | (unsigned)(total + base));
        }
        if (lane == 0) s_base = base;
    }
    __syncthreads();
    if (i < n) g_offsets[i] = s_base + incl - v;
}

// ---------------- atomic-free scatter, 4B packed payload ----------------
__global__ void k_scatter(const int* __restrict__ rows,
                          const int* __restrict__ cols,
                          const float* __restrict__ vals, int nnz) {
    int i = blockIdx.x * blockDim.x + threadIdx.x;
    if (i < nnz) {
        int r = rows[i];
        int p = g_offsets[r] + (int)g_rank[i];
        unsigned pk = ((unsigned)cols[i] << 16)
                    | (unsigned)__half_as_ushort(__float2half_rn(vals[i]));
        __stcs(&g_pack[p], pk);    // streaming: bypass L1
    }
}

// ---------------- warp-per-row gather SpMM (fp16 W & val, fp32 accumulate) ----------------
__global__ void __launch_bounds__(256)
k_spmm(const float* __restrict__ bias, float* __restrict__ out, int n) {
    int gwarp = (blockIdx.x * blockDim.x + threadIdx.x) >> 5;
    int lane  = threadIdx.x & 31;
    if (gwarp >= n) return;
    int start = g_offsets[gwarp];
    int cnt   = g_counts[gwarp];

    float2 acc = ((const float2*)bias)[lane];   // lane owns cols [2l, 2l+1]
    const __half2* __restrict__ wh2 = (const __half2*)g_wh;

    for (int base = 0; base < cnt; base += 32) {
        int k = base + lane;
        unsigned u = (k < cnt) ? g_pack[start + k] : 0u;   // 128B coalesced
        int m = cnt - base; if (m > 32) m = 32;
        #pragma unroll 4
        for (int j = 0; j < m; ++j) {
            unsigned up = __shfl_sync(0xFFFFFFFFu, u, j);  // single shfl per nnz
            int   c = (int)(up >> 16);
            float v = __half2float(__ushort_as_half((unsigned short)(up & 0xFFFFu)));
            float2 wf = __half22float2(wh2[c * 32 + lane]);
            acc.x = fmaf(v, wf.x, acc.x);
            acc.y = fmaf(v, wf.y, acc.y);
        }
    }
    ((float2*)out)[(size_t)gwarp * 32 + lane] = acc;
}

// ---------------- launch ----------------
extern "C" void kernel_launch(void* const* d_in, const int* in_sizes, int n_in,
                              void* d_out, int out_size) {
    const int*   index  = (const int*)d_in[0];    // [2, nnz]
    const float* value  = (const float*)d_in[1];  // [nnz]
    const float* weight = (const float*)d_in[3];  // [in_f, 64]
    const float* bias   = (const float*)d_in[4];  // [64]
    float* out = (float*)d_out;

    int nnz  = in_sizes[1];
    int n    = out_size / OUTF;
    int wtot = in_sizes[3];

    const int* rows = index;
    const int* cols = index + nnz;
    int nb = (n + CHUNK - 1) / CHUNK;

    void* counts_ptr = nullptr;
    cudaGetSymbolAddress(&counts_ptr, g_counts);
    cudaMemsetAsync(counts_ptr, 0, (size_t)n * sizeof(int));

    k_cvt<<<(wtot + 255) / 256, 256>>>(weight, wtot);
    k_hist<<<(nnz + 255) / 256, 256>>>(rows, nnz, nb);
    k_scan<<<nb, CHUNK>>>(n);
    k_scatter<<<(nnz + 255) / 256, 256>>>(rows, cols, value, nnz);

    int blocks = (n * 32 + 255) / 256;
    k_spmm<<<blocks, 256>>>(bias, out, n);
}

// round 6
// speedup vs baseline: 1.2216x; 1.0742x over previous
#include <cuda_runtime.h>
#include <cuda_fp16.h>
#include <stdint.h>

// SparseLinear: out[n,64] = segment_sum(value * W[col,:], rows) + bias
// One-pass grouping: fixed 96-slot bin per row; atomicAdd(count) IS the
// placement. No scan, no scatter pass, no rank array.
// Pipeline: memset counts -> cvt W fp16 -> fill slots -> warp/row SpMM -> fixup.

#define OUTF    64
#define N_MAX   100032
#define NNZ_MAX 4000000
#define INF_MAX 5120
#define S       96            // slots per row (mean 40, max-of-100K ~70)
#define OVF_MAX 4096

__device__ int      g_counts[N_MAX];
__device__ unsigned g_slots[(size_t)N_MAX * S];   // col<<16 | fp16(value)
__device__ int      g_ovfcnt;
__device__ int2     g_ovf[OVF_MAX];               // {row, pack}
__device__ __half   g_wh[INF_MAX * OUTF];

// ---------------- convert W fp32 -> fp16 ----------------
__global__ void k_cvt(const float* __restrict__ W, int total) {
    int i = blockIdx.x * blockDim.x + threadIdx.x;
    if (i < total) g_wh[i] = __float2half_rn(W[i]);
}

// ---------------- one-pass fill: count + place ----------------
__global__ void __launch_bounds__(256)
k_fill(const int* __restrict__ rows, const int* __restrict__ cols,
       const float* __restrict__ vals, int nnz) {
    int base = blockIdx.x * 1024 + threadIdx.x;
    #pragma unroll
    for (int k = 0; k < 4; ++k) {
        int i = base + k * 256;                    // coalesced per iteration
        if (i < nnz) {
            int r = rows[i];
            unsigned pk = ((unsigned)cols[i] << 16)
                        | (unsigned)__half_as_ushort(__float2half_rn(vals[i]));
            int rank = atomicAdd(&g_counts[r], 1);
            if (rank < S) {
                __stcs(&g_slots[(size_t)r * S + rank], pk);
            } else {
                int o = atomicAdd(&g_ovfcnt, 1);
                if (o < OVF_MAX) g_ovf[o] = make_int2(r, (int)pk);
            }
        }
    }
}

// ---------------- warp-per-row gather SpMM (fp16 W & val, fp32 acc) ----------------
__global__ void __launch_bounds__(256)
k_spmm(const float* __restrict__ bias, float* __restrict__ out, int n) {
    int row  = (blockIdx.x * blockDim.x + threadIdx.x) >> 5;
    int lane = threadIdx.x & 31;
    if (row >= n) return;
    int cnt = g_counts[row];
    if (cnt > S) cnt = S;
    const unsigned* __restrict__ sl = &g_slots[(size_t)row * S];

    float2 acc = ((const float2*)bias)[lane];      // lane owns cols [2l, 2l+1]
    const __half2* __restrict__ wh2 = (const __half2*)g_wh;

    for (int base = 0; base < cnt; base += 32) {
        int k = base + lane;
        unsigned u = (k < cnt) ? sl[k] : 0u;       // 128B coalesced (row*384B aligned)
        int m = cnt - base; if (m > 32) m = 32;
        #pragma unroll 4
        for (int j = 0; j < m; ++j) {
            unsigned up = __shfl_sync(0xFFFFFFFFu, u, j);
            int   c = (int)(up >> 16);
            float v = __half2float(__ushort_as_half((unsigned short)(up & 0xFFFFu)));
            float2 wf = __half22float2(wh2[c * 32 + lane]);
            acc.x = fmaf(v, wf.x, acc.x);
            acc.y = fmaf(v, wf.y, acc.y);
        }
    }
    ((float2*)out)[(size_t)row * 32 + lane] = acc;
}

// ---------------- overflow fixup (statistically empty; correctness net) ----------------
__global__ void k_fix(float* __restrict__ out, int n) {
    int cnt = g_ovfcnt;
    if (cnt > OVF_MAX) cnt = OVF_MAX;
    int lane = threadIdx.x & 31;
    int w    = threadIdx.x >> 5;
    for (int i = w; i < cnt; i += 8) {             // one warp per item
        int2 it = g_ovf[i];
        int r = it.x;
        unsigned up = (unsigned)it.y;
        int   c = (int)(up >> 16);
        float v = __half2float(__ushort_as_half((unsigned short)(up & 0xFFFFu)));
        if (r < n) {
            float* o = out + (size_t)r * OUTF;
            #pragma unroll
            for (int q = 0; q < 2; ++q) {
                int cc = lane * 2 + q;
                atomicAdd(&o[cc], v * __half2float(g_wh[c * OUTF + cc]));
            }
        }
    }
}

// ---------------- launch ----------------
extern "C" void kernel_launch(void* const* d_in, const int* in_sizes, int n_in,
                              void* d_out, int out_size) {
    const int*   index  = (const int*)d_in[0];    // [2, nnz]
    const float* value  = (const float*)d_in[1];  // [nnz]
    const float* weight = (const float*)d_in[3];  // [in_f, 64]
    const float* bias   = (const float*)d_in[4];  // [64]
    float* out = (float*)d_out;

    int nnz  = in_sizes[1];
    int n    = out_size / OUTF;
    int wtot = in_sizes[3];

    const int* rows = index;
    const int* cols = index + nnz;

    void* p = nullptr;
    cudaGetSymbolAddress(&p, g_counts);
    cudaMemsetAsync(p, 0, (size_t)n * sizeof(int));
    cudaGetSymbolAddress(&p, g_ovfcnt);
    cudaMemsetAsync(p, 0, sizeof(int));

    k_cvt<<<(wtot + 255) / 256, 256>>>(weight, wtot);
    k_fill<<<(nnz + 1023) / 1024, 256>>>(rows, cols, value, nnz);

    int blocks = (n * 32 + 255) / 256;
    k_spmm<<<blocks, 256>>>(bias, out, n);
    k_fix<<<1, 256>>>(out, n);
}

// round 7
// speedup vs baseline: 1.2389x; 1.0142x over previous
#include <cuda_runtime.h>
#include <cuda_fp16.h>
#include <stdint.h>

// SparseLinear: out[n,64] = segment_sum(value * W[col,:], rows) + bias
// Fixed-slot grouping with 4 column bins (col&3) for W L1-locality.
// Pipeline: memset counts(+ovfcnt) -> fill(+cvt fused) -> spmm(+fixup fused).

#define OUTF    64
#define N_MAX   100032
#define NNZ_MAX 4000000
#define INF_MAX 5120
#define NB      4             // column bins (col & 3)
#define S       32            // slots per (row, bin); mean 10, max-of-400K ~30
#define OVF_MAX 4096
#define CVTB    160           // blocks of k_fill dedicated to W convert

__device__ int      g_counts[N_MAX * NB + 1];     // [+1] = overflow counter
__device__ unsigned g_slots[(size_t)N_MAX * NB * S];   // col<<16 | fp16(value)
__device__ int2     g_ovf[OVF_MAX];               // {row, pack}
__device__ __half   g_wh[INF_MAX * OUTF];

// ---------------- fill: cvt (first CVTB blocks) + count-and-place ----------------
__global__ void __launch_bounds__(256)
k_fill(const int* __restrict__ rows, const int* __restrict__ cols,
       const float* __restrict__ vals, int nnz,
       const float* __restrict__ W, int wtot, int n) {
    int b = blockIdx.x, t = threadIdx.x;
    if (b < CVTB) {    // convert W fp32 -> fp16, grid-stride
        for (int i = b * 256 + t; i < wtot; i += CVTB * 256)
            g_wh[i] = __float2half_rn(W[i]);
        return;
    }
    int* ovfcnt = &g_counts[n * NB];
    int base = (b - CVTB) * 1024 + t;
    #pragma unroll
    for (int k = 0; k < 4; ++k) {
        int i = base + k * 256;                    // coalesced per iteration
        if (i < nnz) {
            int r = rows[i];
            int c = cols[i];
            unsigned pk = ((unsigned)c << 16)
                        | (unsigned)__half_as_ushort(__float2half_rn(vals[i]));
            int cidx = (r << 2) | (c & (NB - 1));
            int rank = atomicAdd(&g_counts[cidx], 1);
            if (rank < S) {
                __stcs(&g_slots[((size_t)cidx << 5) + rank], pk);
            } else {
                int o = atomicAdd(ovfcnt, 1);
                if (o < OVF_MAX) g_ovf[o] = make_int2(r, (int)pk);
            }
        }
    }
}

// ---------------- warp-per-row SpMM over 4 col bins (+inline overflow fixup) ----------------
__global__ void __launch_bounds__(256)
k_spmm(const float* __restrict__ bias, float* __restrict__ out, int n) {
    int row  = (blockIdx.x * blockDim.x + threadIdx.x) >> 5;
    int lane = threadIdx.x & 31;
    if (row >= n) return;

    float2 acc = ((const float2*)bias)[lane];      // lane owns cols [2l, 2l+1]
    const __half2* __restrict__ wh2 = (const __half2*)g_wh;
    bool ovf = false;

    #pragma unroll
    for (int bin = 0; bin < NB; ++bin) {
        int cidx = (row << 2) | bin;
        int cnt = g_counts[cidx];                  // warp-uniform
        if (cnt > S) { cnt = S; ovf = true; }
        unsigned u = (lane < cnt) ? g_slots[((size_t)cidx << 5) + lane] : 0u;
        #pragma unroll 4
        for (int j = 0; j < cnt; ++j) {
            unsigned up = __shfl_sync(0xFFFFFFFFu, u, j);
            int   c = (int)(up >> 16);
            float v = __half2float(__ushort_as_half((unsigned short)(up & 0xFFFFu)));
            float2 wf = __half22float2(wh2[c * 32 + lane]);
            acc.x = fmaf(v, wf.x, acc.x);
            acc.y = fmaf(v, wf.y, acc.y);
        }
    }

    // inline overflow fixup: statistically 0 items; scan is warp-broadcast.
    int oc = g_counts[n * NB];
    if (oc > 0) {
        if (oc > OVF_MAX) oc = OVF_MAX;            // truly pathological clamp
        for (int i = 0; i < oc; ++i) {
            int2 it = g_ovf[i];
            if (it.x == row) {
                unsigned up = (unsigned)it.y;
                int   c = (int)(up >> 16);
                float v = __half2float(__ushort_as_half((unsigned short)(up & 0xFFFFu)));
                float2 wf = __half22float2(wh2[c * 32 + lane]);
                acc.x = fmaf(v, wf.x, acc.x);
                acc.y = fmaf(v, wf.y, acc.y);
            }
        }
        (void)ovf;
    }

    ((float2*)out)[(size_t)row * 32 + lane] = acc;
}

// ---------------- launch ----------------
extern "C" void kernel_launch(void* const* d_in, const int* in_sizes, int n_in,
                              void* d_out, int out_size) {
    const int*   index  = (const int*)d_in[0];    // [2, nnz]
    const float* value  = (const float*)d_in[1];  // [nnz]
    const float* weight = (const float*)d_in[3];  // [in_f, 64]
    const float* bias   = (const float*)d_in[4];  // [64]
    float* out = (float*)d_out;

    int nnz  = in_sizes[1];
    int n    = out_size / OUTF;
    int wtot = in_sizes[3];

    const int* rows = index;
    const int* cols = index + nnz;

    void* p = nullptr;
    cudaGetSymbolAddress(&p, g_counts);
    cudaMemsetAsync(p, 0, ((size_t)n * NB + 1) * sizeof(int));

    int fb = CVTB + (nnz + 1023) / 1024;
    k_fill<<<fb, 256>>>(rows, cols, value, nnz, weight, wtot, n);

    int blocks = (n * 32 + 255) / 256;
    k_spmm<<<blocks, 256>>>(bias, out, n);
}